// round 1
// baseline (speedup 1.0000x reference)
#include <cuda_runtime.h>
#include <math.h>

#define BATCH 16384
#define DD 4096
#define HH 128
#define EE 64
#define NS 5

// scratch for h = relu(x@W1+b1): 16384 x 128 fp32 = 8 MB
__device__ float g_h[(size_t)BATCH * HH];

// ---------------------------------------------------------------------------
// GEMM1: h[B,128] = relu(x[B,4096] @ W1[4096,128] + b1)
// Tile: 64 rows x 128 cols (full H) per CTA, BK=32, 256 threads, 8x4 microtile.
// ---------------------------------------------------------------------------
__global__ __launch_bounds__(256) void gemm1_kernel(const float* __restrict__ x,
                                                    const float* __restrict__ W1,
                                                    const float* __restrict__ b1) {
    __shared__ float As[32][68];   // [k][m], padded stride 68 (272B rows, 16B aligned)
    __shared__ float Bs[32][HH];   // [k][n]

    const int tid = threadIdx.x;
    const int tx = tid & 31;   // n/4
    const int ty = tid >> 5;   // m/8
    const int rowBase = blockIdx.x * 64;

    float acc[8][4];
#pragma unroll
    for (int m = 0; m < 8; m++)
#pragma unroll
        for (int n = 0; n < 4; n++) acc[m][n] = 0.f;

    const float* xg = x + (size_t)rowBase * DD;

    for (int k0 = 0; k0 < DD; k0 += 32) {
        // load x tile 64x32 (transposed into As)
#pragma unroll
        for (int l = 0; l < 2; l++) {
            int i = tid + 256 * l;          // 0..511
            int r = i >> 3;                 // 0..63
            int kq = (i & 7) * 4;           // 0..28
            float4 v = *(const float4*)(xg + (size_t)r * DD + (k0 + kq));
            As[kq + 0][r] = v.x;
            As[kq + 1][r] = v.y;
            As[kq + 2][r] = v.z;
            As[kq + 3][r] = v.w;
        }
        // load W1 tile 32x128
#pragma unroll
        for (int l = 0; l < 4; l++) {
            int i = tid + 256 * l;          // 0..1023
            int kr = i >> 5;                // 0..31
            int nc = (i & 31) * 4;          // 0..124
            *(float4*)&Bs[kr][nc] = *(const float4*)(W1 + (size_t)(k0 + kr) * HH + nc);
        }
        __syncthreads();

#pragma unroll
        for (int k = 0; k < 32; k++) {
            // A reads are warp-broadcast (ty constant within a warp)
            float4 a0 = *(float4*)&As[k][ty * 8];
            float4 a1 = *(float4*)&As[k][ty * 8 + 4];
            float4 bv = *(float4*)&Bs[k][tx * 4];
            float a[8] = {a0.x, a0.y, a0.z, a0.w, a1.x, a1.y, a1.z, a1.w};
            float bb[4] = {bv.x, bv.y, bv.z, bv.w};
#pragma unroll
            for (int m = 0; m < 8; m++)
#pragma unroll
                for (int n = 0; n < 4; n++)
                    acc[m][n] = fmaf(a[m], bb[n], acc[m][n]);
        }
        __syncthreads();
    }

    // bias + relu + store
    float4 bv = *(const float4*)&b1[tx * 4];
#pragma unroll
    for (int m = 0; m < 8; m++) {
        int row = rowBase + ty * 8 + m;
        float4 o;
        o.x = fmaxf(acc[m][0] + bv.x, 0.f);
        o.y = fmaxf(acc[m][1] + bv.y, 0.f);
        o.z = fmaxf(acc[m][2] + bv.z, 0.f);
        o.w = fmaxf(acc[m][3] + bv.w, 0.f);
        *(float4*)&g_h[(size_t)row * HH + tx * 4] = o;
    }
}

// ---------------------------------------------------------------------------
// Epilogue: one warp per row. 8 rows / 256-thread block. W2 staged in smem.
// Each lane owns experts e0=2*lane, e1=2*lane+1.
// ---------------------------------------------------------------------------
__global__ __launch_bounds__(256) void epilogue_kernel(const float* __restrict__ W2,
                                                       const float* __restrict__ b2,
                                                       const float* __restrict__ m1,
                                                       const float* __restrict__ m2,
                                                       float* __restrict__ out,
                                                       int B) {
    __shared__ float ws2[HH * EE];   // 32 KB
    __shared__ float hs[8][HH];      // per-warp masked h (4 KB)

    const int tid = threadIdx.x;
    const int lane = tid & 31;
    const int warp = tid >> 5;

    // stage W2
#pragma unroll
    for (int l = 0; l < 8; l++) {
        int i = (tid + 256 * l) * 4;
        *(float4*)&ws2[i] = *(const float4*)&W2[i];
    }
    __syncthreads();

    const int row = blockIdx.x * 8 + warp;
    const float SCALE = 1.4285714285714286f;  // 1/(1-0.3) as in reference (double->f32)

    // h row: each lane holds its 4 elements
    float4 hreg = *(const float4*)&g_h[(size_t)row * HH + lane * 4];
    float2 b2v = *(const float2*)&b2[lane * 2];

    float lg0[NS], lg1[NS];
#pragma unroll
    for (int s = 0; s < NS; s++) {
        // masked h into smem (own 4 elems)
        float4 u = *(const float4*)&m1[(size_t)s * B * HH + (size_t)row * HH + lane * 4];
        float4 o;
        o.x = (u.x >= 0.3f) ? hreg.x * SCALE : 0.f;
        o.y = (u.y >= 0.3f) ? hreg.y * SCALE : 0.f;
        o.z = (u.z >= 0.3f) ? hreg.z * SCALE : 0.f;
        o.w = (u.w >= 0.3f) ? hreg.w * SCALE : 0.f;
        *(float4*)&hs[warp][lane * 4] = o;
        __syncwarp();

        float a0 = 0.f, a1 = 0.f;
#pragma unroll
        for (int j = 0; j < HH; j++) {
            float hj = hs[warp][j];                       // broadcast
            float2 w = *(float2*)&ws2[j * EE + lane * 2]; // conflict-free
            a0 = fmaf(hj, w.x, a0);
            a1 = fmaf(hj, w.y, a1);
        }
        float2 mu = *(const float2*)&m2[(size_t)s * B * EE + (size_t)row * EE + lane * 2];
        lg0[s] = (a0 + b2v.x) * ((mu.x >= 0.3f) ? SCALE : 0.f);
        lg1[s] = (a1 + b2v.y) * ((mu.y >= 0.3f) ? SCALE : 0.f);
        __syncwarp();   // protect hs before next sample overwrites
    }

    // mean logits and its softmax
    float ml0 = (lg0[0] + lg0[1] + lg0[2] + lg0[3] + lg0[4]) * 0.2f;
    float ml1 = (lg1[0] + lg1[1] + lg1[2] + lg1[3] + lg1[4]) * 0.2f;

    float mx = fmaxf(ml0, ml1);
#pragma unroll
    for (int off = 16; off; off >>= 1) mx = fmaxf(mx, __shfl_xor_sync(0xffffffffu, mx, off));
    float p0 = expf(ml0 - mx);
    float p1 = expf(ml1 - mx);
    float sm = p0 + p1;
#pragma unroll
    for (int off = 16; off; off >>= 1) sm += __shfl_xor_sync(0xffffffffu, sm, off);
    float pr0 = p0 / sm;
    float pr1 = p1 / sm;

    // per-sample softmax
    float ap0[NS], ap1[NS];
#pragma unroll
    for (int s = 0; s < NS; s++) {
        float mxs = fmaxf(lg0[s], lg1[s]);
#pragma unroll
        for (int off = 16; off; off >>= 1) mxs = fmaxf(mxs, __shfl_xor_sync(0xffffffffu, mxs, off));
        float e0 = expf(lg0[s] - mxs);
        float e1 = expf(lg1[s] - mxs);
        float ss = e0 + e1;
#pragma unroll
        for (int off = 16; off; off >>= 1) ss += __shfl_xor_sync(0xffffffffu, ss, off);
        ap0[s] = e0 / ss;
        ap1[s] = e1 / ss;
    }

    // std over samples (ddof=1), then mean over experts
    float mp0 = (ap0[0] + ap0[1] + ap0[2] + ap0[3] + ap0[4]) * 0.2f;
    float mp1 = (ap1[0] + ap1[1] + ap1[2] + ap1[3] + ap1[4]) * 0.2f;
    float v0 = 0.f, v1 = 0.f;
#pragma unroll
    for (int s = 0; s < NS; s++) {
        float d0 = ap0[s] - mp0;
        float d1 = ap1[s] - mp1;
        v0 = fmaf(d0, d0, v0);
        v1 = fmaf(d1, d1, v1);
    }
    float stds = sqrtf(v0 * 0.25f) + sqrtf(v1 * 0.25f);
#pragma unroll
    for (int off = 16; off; off >>= 1) stds += __shfl_xor_sync(0xffffffffu, stds, off);
    float unc = stds / 64.0f;

    // top-4 with jax tie-break (equal value -> lower index)
    float q0 = pr0, q1 = pr1;
    const int i0 = lane * 2, i1 = lane * 2 + 1;
    float fp[4];
    int fi[4];
#pragma unroll
    for (int k = 0; k < 4; k++) {
        float bp;
        int bi;
        if (q0 >= q1) { bp = q0; bi = i0; }   // tie -> lower index
        else          { bp = q1; bi = i1; }
#pragma unroll
        for (int off = 16; off; off >>= 1) {
            float op = __shfl_xor_sync(0xffffffffu, bp, off);
            int oi = __shfl_xor_sync(0xffffffffu, bi, off);
            if (op > bp || (op == bp && oi < bi)) { bp = op; bi = oi; }
        }
        fp[k] = bp;
        fi[k] = bi;
        if (bi == i0) q0 = -1.f;
        if (bi == i1) q1 = -1.f;
    }

    if (lane == 0) {
        bool uncertain = unc > 0.3f;
        size_t pb = (size_t)4 * B;       // probs base
        size_t ub = (size_t)8 * B;       // uncertainty base
        out[(size_t)row * 4 + 0] = (float)fi[0];
        out[(size_t)row * 4 + 1] = (float)fi[1];
        out[(size_t)row * 4 + 2] = uncertain ? (float)fi[2] : -1.0f;
        out[(size_t)row * 4 + 3] = uncertain ? (float)fi[3] : -1.0f;
        out[pb + (size_t)row * 4 + 0] = fp[0];
        out[pb + (size_t)row * 4 + 1] = fp[1];
        out[pb + (size_t)row * 4 + 2] = uncertain ? fp[2] : 0.0f;
        out[pb + (size_t)row * 4 + 3] = uncertain ? fp[3] : 0.0f;
        out[ub + row] = unc;
    }
}

extern "C" void kernel_launch(void* const* d_in, const int* in_sizes, int n_in,
                              void* d_out, int out_size) {
    const float* x  = (const float*)d_in[0];
    const float* W1 = (const float*)d_in[1];
    const float* b1 = (const float*)d_in[2];
    const float* W2 = (const float*)d_in[3];
    const float* b2 = (const float*)d_in[4];
    const float* m1 = (const float*)d_in[5];
    const float* m2 = (const float*)d_in[6];
    float* out = (float*)d_out;

    int B = in_sizes[0] / DD;   // 16384

    gemm1_kernel<<<B / 64, 256>>>(x, W1, b1);
    epilogue_kernel<<<B / 8, 256>>>(W2, b2, m1, m2, out, B);
}

// round 2
// speedup vs baseline: 1.0026x; 1.0026x over previous
#include <cuda_runtime.h>
#include <math.h>

#define BATCH 16384
#define DD 4096
#define HH 128
#define EE 64
#define NS 5

// scratch for h = relu(x@W1+b1): 16384 x 128 fp32 = 8 MB
__device__ float g_h[(size_t)BATCH * HH];

// ---------------------------------------------------------------------------
// GEMM1: h[B,128] = relu(x[B,4096] @ W1[4096,128] + b1)
// Tile: 64 rows x 128 cols (full H) per CTA, BK=32, 256 threads, 8x4 microtile.
// ---------------------------------------------------------------------------
__global__ __launch_bounds__(256) void gemm1_kernel(const float* __restrict__ x,
                                                    const float* __restrict__ W1,
                                                    const float* __restrict__ b1) {
    __shared__ float As[32][68];   // [k][m], padded stride 68 (272B rows, 16B aligned)
    __shared__ float Bs[32][HH];   // [k][n]

    const int tid = threadIdx.x;
    const int tx = tid & 31;   // n/4
    const int ty = tid >> 5;   // m/8
    const int rowBase = blockIdx.x * 64;

    float acc[8][4];
#pragma unroll
    for (int m = 0; m < 8; m++)
#pragma unroll
        for (int n = 0; n < 4; n++) acc[m][n] = 0.f;

    const float* xg = x + (size_t)rowBase * DD;

    for (int k0 = 0; k0 < DD; k0 += 32) {
        // load x tile 64x32 (transposed into As)
#pragma unroll
        for (int l = 0; l < 2; l++) {
            int i = tid + 256 * l;          // 0..511
            int r = i >> 3;                 // 0..63
            int kq = (i & 7) * 4;           // 0..28
            float4 v = *(const float4*)(xg + (size_t)r * DD + (k0 + kq));
            As[kq + 0][r] = v.x;
            As[kq + 1][r] = v.y;
            As[kq + 2][r] = v.z;
            As[kq + 3][r] = v.w;
        }
        // load W1 tile 32x128
#pragma unroll
        for (int l = 0; l < 4; l++) {
            int i = tid + 256 * l;          // 0..1023
            int kr = i >> 5;                // 0..31
            int nc = (i & 31) * 4;          // 0..124
            *(float4*)&Bs[kr][nc] = *(const float4*)(W1 + (size_t)(k0 + kr) * HH + nc);
        }
        __syncthreads();

#pragma unroll
        for (int k = 0; k < 32; k++) {
            // A reads are warp-broadcast (ty constant within a warp)
            float4 a0 = *(float4*)&As[k][ty * 8];
            float4 a1 = *(float4*)&As[k][ty * 8 + 4];
            float4 bv = *(float4*)&Bs[k][tx * 4];
            float a[8] = {a0.x, a0.y, a0.z, a0.w, a1.x, a1.y, a1.z, a1.w};
            float bb[4] = {bv.x, bv.y, bv.z, bv.w};
#pragma unroll
            for (int m = 0; m < 8; m++)
#pragma unroll
                for (int n = 0; n < 4; n++)
                    acc[m][n] = fmaf(a[m], bb[n], acc[m][n]);
        }
        __syncthreads();
    }

    // bias + relu + store
    float4 bv = *(const float4*)&b1[tx * 4];
#pragma unroll
    for (int m = 0; m < 8; m++) {
        int row = rowBase + ty * 8 + m;
        float4 o;
        o.x = fmaxf(acc[m][0] + bv.x, 0.f);
        o.y = fmaxf(acc[m][1] + bv.y, 0.f);
        o.z = fmaxf(acc[m][2] + bv.z, 0.f);
        o.w = fmaxf(acc[m][3] + bv.w, 0.f);
        *(float4*)&g_h[(size_t)row * HH + tx * 4] = o;
    }
}

// ---------------------------------------------------------------------------
// Epilogue: one warp per row. 8 rows / 256-thread block. W2 staged in smem.
// Each lane owns experts e0=2*lane, e1=2*lane+1.
// ---------------------------------------------------------------------------
__global__ __launch_bounds__(256) void epilogue_kernel(const float* __restrict__ W2,
                                                       const float* __restrict__ b2,
                                                       const float* __restrict__ m1,
                                                       const float* __restrict__ m2,
                                                       float* __restrict__ out,
                                                       int B) {
    __shared__ float ws2[HH * EE];   // 32 KB
    __shared__ float hs[8][HH];      // per-warp masked h (4 KB)

    const int tid = threadIdx.x;
    const int lane = tid & 31;
    const int warp = tid >> 5;

    // stage W2
#pragma unroll
    for (int l = 0; l < 8; l++) {
        int i = (tid + 256 * l) * 4;
        *(float4*)&ws2[i] = *(const float4*)&W2[i];
    }
    __syncthreads();

    const int row = blockIdx.x * 8 + warp;
    const float SCALE = 1.4285714285714286f;  // 1/(1-0.3) as in reference (double->f32)

    // h row: each lane holds its 4 elements
    float4 hreg = *(const float4*)&g_h[(size_t)row * HH + lane * 4];
    float2 b2v = *(const float2*)&b2[lane * 2];

    float lg0[NS], lg1[NS];
#pragma unroll
    for (int s = 0; s < NS; s++) {
        // masked h into smem (own 4 elems)
        float4 u = *(const float4*)&m1[(size_t)s * B * HH + (size_t)row * HH + lane * 4];
        float4 o;
        o.x = (u.x >= 0.3f) ? hreg.x * SCALE : 0.f;
        o.y = (u.y >= 0.3f) ? hreg.y * SCALE : 0.f;
        o.z = (u.z >= 0.3f) ? hreg.z * SCALE : 0.f;
        o.w = (u.w >= 0.3f) ? hreg.w * SCALE : 0.f;
        *(float4*)&hs[warp][lane * 4] = o;
        __syncwarp();

        float a0 = 0.f, a1 = 0.f;
#pragma unroll
        for (int j = 0; j < HH; j++) {
            float hj = hs[warp][j];                       // broadcast
            float2 w = *(float2*)&ws2[j * EE + lane * 2]; // conflict-free
            a0 = fmaf(hj, w.x, a0);
            a1 = fmaf(hj, w.y, a1);
        }
        float2 mu = *(const float2*)&m2[(size_t)s * B * EE + (size_t)row * EE + lane * 2];
        lg0[s] = (a0 + b2v.x) * ((mu.x >= 0.3f) ? SCALE : 0.f);
        lg1[s] = (a1 + b2v.y) * ((mu.y >= 0.3f) ? SCALE : 0.f);
        __syncwarp();   // protect hs before next sample overwrites
    }

    // mean logits and its softmax
    float ml0 = (lg0[0] + lg0[1] + lg0[2] + lg0[3] + lg0[4]) * 0.2f;
    float ml1 = (lg1[0] + lg1[1] + lg1[2] + lg1[3] + lg1[4]) * 0.2f;

    float mx = fmaxf(ml0, ml1);
#pragma unroll
    for (int off = 16; off; off >>= 1) mx = fmaxf(mx, __shfl_xor_sync(0xffffffffu, mx, off));
    float p0 = expf(ml0 - mx);
    float p1 = expf(ml1 - mx);
    float sm = p0 + p1;
#pragma unroll
    for (int off = 16; off; off >>= 1) sm += __shfl_xor_sync(0xffffffffu, sm, off);
    float pr0 = p0 / sm;
    float pr1 = p1 / sm;

    // per-sample softmax
    float ap0[NS], ap1[NS];
#pragma unroll
    for (int s = 0; s < NS; s++) {
        float mxs = fmaxf(lg0[s], lg1[s]);
#pragma unroll
        for (int off = 16; off; off >>= 1) mxs = fmaxf(mxs, __shfl_xor_sync(0xffffffffu, mxs, off));
        float e0 = expf(lg0[s] - mxs);
        float e1 = expf(lg1[s] - mxs);
        float ss = e0 + e1;
#pragma unroll
        for (int off = 16; off; off >>= 1) ss += __shfl_xor_sync(0xffffffffu, ss, off);
        ap0[s] = e0 / ss;
        ap1[s] = e1 / ss;
    }

    // std over samples (ddof=1), then mean over experts
    float mp0 = (ap0[0] + ap0[1] + ap0[2] + ap0[3] + ap0[4]) * 0.2f;
    float mp1 = (ap1[0] + ap1[1] + ap1[2] + ap1[3] + ap1[4]) * 0.2f;
    float v0 = 0.f, v1 = 0.f;
#pragma unroll
    for (int s = 0; s < NS; s++) {
        float d0 = ap0[s] - mp0;
        float d1 = ap1[s] - mp1;
        v0 = fmaf(d0, d0, v0);
        v1 = fmaf(d1, d1, v1);
    }
    float stds = sqrtf(v0 * 0.25f) + sqrtf(v1 * 0.25f);
#pragma unroll
    for (int off = 16; off; off >>= 1) stds += __shfl_xor_sync(0xffffffffu, stds, off);
    float unc = stds / 64.0f;

    // top-4 with jax tie-break (equal value -> lower index)
    float q0 = pr0, q1 = pr1;
    const int i0 = lane * 2, i1 = lane * 2 + 1;
    float fp[4];
    int fi[4];
#pragma unroll
    for (int k = 0; k < 4; k++) {
        float bp;
        int bi;
        if (q0 >= q1) { bp = q0; bi = i0; }   // tie -> lower index
        else          { bp = q1; bi = i1; }
#pragma unroll
        for (int off = 16; off; off >>= 1) {
            float op = __shfl_xor_sync(0xffffffffu, bp, off);
            int oi = __shfl_xor_sync(0xffffffffu, bi, off);
            if (op > bp || (op == bp && oi < bi)) { bp = op; bi = oi; }
        }
        fp[k] = bp;
        fi[k] = bi;
        if (bi == i0) q0 = -1.f;
        if (bi == i1) q1 = -1.f;
    }

    if (lane == 0) {
        bool uncertain = unc > 0.3f;
        size_t pb = (size_t)4 * B;       // probs base
        size_t ub = (size_t)8 * B;       // uncertainty base
        out[(size_t)row * 4 + 0] = (float)fi[0];
        out[(size_t)row * 4 + 1] = (float)fi[1];
        out[(size_t)row * 4 + 2] = uncertain ? (float)fi[2] : -1.0f;
        out[(size_t)row * 4 + 3] = uncertain ? (float)fi[3] : -1.0f;
        out[pb + (size_t)row * 4 + 0] = fp[0];
        out[pb + (size_t)row * 4 + 1] = fp[1];
        out[pb + (size_t)row * 4 + 2] = uncertain ? fp[2] : 0.0f;
        out[pb + (size_t)row * 4 + 3] = uncertain ? fp[3] : 0.0f;
        out[ub + row] = unc;
    }
}

extern "C" void kernel_launch(void* const* d_in, const int* in_sizes, int n_in,
                              void* d_out, int out_size) {
    const float* x  = (const float*)d_in[0];
    const float* W1 = (const float*)d_in[1];
    const float* b1 = (const float*)d_in[2];
    const float* W2 = (const float*)d_in[3];
    const float* b2 = (const float*)d_in[4];
    const float* m1 = (const float*)d_in[5];
    const float* m2 = (const float*)d_in[6];
    float* out = (float*)d_out;

    int B = in_sizes[0] / DD;   // 16384

    gemm1_kernel<<<B / 64, 256>>>(x, W1, b1);
    epilogue_kernel<<<B / 8, 256>>>(W2, b2, m1, m2, out, B);
}